// round 1
// baseline (speedup 1.0000x reference)
#include <cuda_runtime.h>
#include <math.h>

#define NH   32
#define HD   128
#define BB   4
#define QL   64
#define CTX  4096
#define HID  4096
#define TOTAL_KV (CTX + QL)      // 4160
#define TK   64
#define NTILE (TOTAL_KV / TK)    // 65

// Scratch (static device globals; no allocation in kernel_launch)
__device__ float g_qproj[BB * QL * HID];          // 4 MB  [m, h*128+d]
__device__ float g_q[BB * NH * QL * HD];          // 4 MB  [b,h,q,d]
__device__ float g_attn[BB * QL * HID];           // 4 MB  [m, h*128+d]

// ---------------------------------------------------------------------------
// Generic fp32 tiled GEMM: C[M,N] = A[M,K] @ B[K,N], B row stride = ldb.
// 64x64 block tile, BK=16, 256 threads, 4x4 per-thread micro-tile.
// ---------------------------------------------------------------------------
__global__ __launch_bounds__(256) void gemm64_kernel(
    const float* __restrict__ A, const float* __restrict__ Bm,
    float* __restrict__ C, int M, int N, int K, int ldb)
{
    __shared__ float As[16][68];   // [k][m], padded
    __shared__ float Bs[16][68];   // [k][n], padded

    const int t  = threadIdx.x;
    const int tx = t & 15, ty = t >> 4;
    const int bx = blockIdx.x, by = blockIdx.y;

    const float* Ab = A  + (size_t)by * 64 * K;
    const float* Bb = Bm + (size_t)bx * 64;

    const int ar = t >> 2, ak = (t & 3) << 2;   // A: 64 rows x 16 k, float4 along k
    const int br = t >> 4, bc = (t & 15) << 2;  // B: 16 rows x 64 n, float4 along n

    float acc[4][4] = {};

    for (int k0 = 0; k0 < K; k0 += 16) {
        float4 av = *(const float4*)(Ab + (size_t)ar * K + k0 + ak);
        As[ak + 0][ar] = av.x; As[ak + 1][ar] = av.y;
        As[ak + 2][ar] = av.z; As[ak + 3][ar] = av.w;
        *(float4*)&Bs[br][bc] = *(const float4*)(Bb + (size_t)(k0 + br) * ldb + bc);
        __syncthreads();
#pragma unroll
        for (int k = 0; k < 16; k++) {
            float4 a  = *(float4*)&As[k][ty << 2];
            float4 bv = *(float4*)&Bs[k][tx << 2];
            float  aa[4] = {a.x, a.y, a.z, a.w};
            float  vv[4] = {bv.x, bv.y, bv.z, bv.w};
#pragma unroll
            for (int i = 0; i < 4; i++)
#pragma unroll
                for (int j = 0; j < 4; j++)
                    acc[i][j] += aa[i] * vv[j];
        }
        __syncthreads();
    }
#pragma unroll
    for (int i = 0; i < 4; i++) {
        float4 o = make_float4(acc[i][0], acc[i][1], acc[i][2], acc[i][3]);
        *(float4*)&C[(size_t)(by * 64 + (ty << 2) + i) * N + bx * 64 + (tx << 2)] = o;
    }
}

// ---------------------------------------------------------------------------
// Fused double-RMSNorm + RoPE on Q.
// grid = B*QL*NH blocks, 128 threads (one per d).
// In:  g_qproj[m, h*128+d]   Out: g_q[((b*NH+h)*QL+q)*HD + d]
// ---------------------------------------------------------------------------
__global__ __launch_bounds__(128) void qnorm_rope_kernel(
    const float* __restrict__ qproj, const float* __restrict__ w,
    const float* __restrict__ cosp, const float* __restrict__ sinp,
    float* __restrict__ qout)
{
    const int blk = blockIdx.x;
    const int h = blk & 31;
    const int m = blk >> 5;          // b*64 + q
    const int b = m >> 6;
    const int q = m & 63;
    const int d = threadIdx.x;

    __shared__ float red[4];
    __shared__ float zbuf[128];

    float x = qproj[(size_t)m * HID + h * HD + d];

    // pass 1: mean(x^2)
    float v = x * x;
#pragma unroll
    for (int o = 16; o > 0; o >>= 1) v += __shfl_down_sync(0xffffffffu, v, o);
    if ((d & 31) == 0) red[d >> 5] = v;
    __syncthreads();
    float mean1 = (red[0] + red[1] + red[2] + red[3]) * (1.0f / 128.0f);
    float y = x * rsqrtf(mean1 + 1e-6f) * w[d];
    __syncthreads();

    // pass 2: mean(y^2)
    v = y * y;
#pragma unroll
    for (int o = 16; o > 0; o >>= 1) v += __shfl_down_sync(0xffffffffu, v, o);
    if ((d & 31) == 0) red[d >> 5] = v;
    __syncthreads();
    float mean2 = (red[0] + red[1] + red[2] + red[3]) * (1.0f / 128.0f);
    float z = y * rsqrtf(mean2 + 1e-6f) * w[d];

    zbuf[d] = z;
    __syncthreads();

    const int pos = CTX + q;
    float rot = (d < 64) ? -zbuf[d + 64] : zbuf[d - 64];
    float o = z * cosp[(size_t)pos * HD + d] + rot * sinp[(size_t)pos * HD + d];

    qout[(((size_t)(b * NH + h) * QL) + q) * HD + d] = o;
}

// ---------------------------------------------------------------------------
// Flash attention. One block per (b,h). 256 threads.
// V tile = raw concat(target_hidden, hidden_states) slice (v is PRE-rope k).
// K tile = RoPE(V tile), built in smem (transposed [d][i]).
// Q pre-scaled by 1/sqrt(D), stored transposed [d][r].
// Online softmax with per-row m/l in smem.
// ---------------------------------------------------------------------------
__global__ __launch_bounds__(256, 1) void attn_kernel(
    const float* __restrict__ qin,      // [b,h,q,d]
    const float* __restrict__ target,   // [b, CTX, HID]
    const float* __restrict__ hidden,   // [b, QL, HID]
    const float* __restrict__ cosp, const float* __restrict__ sinp,
    float* __restrict__ out)            // [b, q, h*128+d]
{
    extern __shared__ float sm[];
    float* qT  = sm;                    // [128][68]  q^T * scale
    float* kT  = qT + 128 * 68;         // [128][68]  k^T (roped)
    float* vS  = kT + 128 * 68;         // [64][132]  raw v tile
    float* pT  = vS + 64 * 132;         // [64][68]   scores^T: [key][qrow]
    float* m_s = pT + 64 * 68;          // [64]
    float* l_s = m_s + 64;              // [64]
    float* al_s = l_s + 64;             // [64]

    const int h = blockIdx.x;
    const int b = blockIdx.y;
    const int t = threadIdx.x;
    const float scale = 0.08838834764831845f;   // 1/sqrt(128)

    // ---- load Q (64 x 128) transposed, pre-scaled ----
    const float* qb = qin + ((size_t)(b * NH + h) * QL) * HD;
    for (int idx = t; idx < QL * HD / 4; idx += 256) {
        int r  = idx >> 5;            // 32 float4 per row
        int c4 = (idx & 31) << 2;
        float4 v = *(const float4*)(qb + r * HD + c4);
        qT[(c4 + 0) * 68 + r] = v.x * scale;
        qT[(c4 + 1) * 68 + r] = v.y * scale;
        qT[(c4 + 2) * 68 + r] = v.z * scale;
        qT[(c4 + 3) * 68 + r] = v.w * scale;
    }
    if (t < 64) { m_s[t] = -1e30f; l_s[t] = 0.0f; }

    float accO[4][8] = {};
    const int oty = t >> 4;           // O rows oty*4..+3
    const int otx = t & 15;           // O cols otx*8..+7
    const int sty = t >> 4;           // S rows sty*4..+3
    const int stx = t & 15;           // S cols stx*4..+3
    __syncthreads();

    for (int tile = 0; tile < NTILE; tile++) {
        const int p0 = tile * TK;

        // ---- load raw V tile (64 x 128) ----
        for (int idx = t; idx < TK * HD / 4; idx += 256) {
            int i  = idx >> 5;
            int c4 = (idx & 31) << 2;
            int p  = p0 + i;
            const float* src = (p < CTX)
                ? (target + ((size_t)b * CTX + p) * HID + h * HD)
                : (hidden + ((size_t)b * QL + (p - CTX)) * HID + h * HD);
            *(float4*)&vS[i * 132 + c4] = *(const float4*)(src + c4);
        }
        __syncthreads();

        // ---- K = RoPE(V), stored transposed kT[d][i] ----
        for (int idx = t; idx < TK * HD; idx += 256) {
            int i = idx >> 7;
            int d = idx & 127;
            int p = p0 + i;
            float x   = vS[i * 132 + d];
            float rot = (d < 64) ? -vS[i * 132 + d + 64] : vS[i * 132 + d - 64];
            kT[d * 68 + i] = x * cosp[(size_t)p * HD + d] + rot * sinp[(size_t)p * HD + d];
        }
        __syncthreads();

        // ---- scores: S[r][c] = sum_d qT[d][r]*kT[d][c]  (4x4 micro-tile) ----
        float sacc[4][4] = {};
#pragma unroll 4
        for (int k = 0; k < HD; k++) {
            float4 a  = *(float4*)&qT[k * 68 + (sty << 2)];
            float4 bv = *(float4*)&kT[k * 68 + (stx << 2)];
            float aa[4] = {a.x, a.y, a.z, a.w};
            float vv[4] = {bv.x, bv.y, bv.z, bv.w};
#pragma unroll
            for (int i = 0; i < 4; i++)
#pragma unroll
                for (int j = 0; j < 4; j++)
                    sacc[i][j] += aa[i] * vv[j];
        }

        // ---- write scores transposed for row scans ----
#pragma unroll
        for (int j = 0; j < 4; j++)
#pragma unroll
            for (int i = 0; i < 4; i++)
                pT[((stx << 2) + j) * 68 + (sty << 2) + i] = sacc[i][j];
        __syncthreads();

        // ---- per-row running max / alpha ----
        if (t < 64) {
            float tm = -1e30f;
#pragma unroll 8
            for (int c = 0; c < TK; c++) tm = fmaxf(tm, pT[c * 68 + t]);
            float mold = m_s[t];
            float mnew = fmaxf(mold, tm);
            al_s[t] = __expf(mold - mnew);
            m_s[t]  = mnew;
        }
        __syncthreads();

        // ---- exponentiate own entries ----
#pragma unroll
        for (int i = 0; i < 4; i++) {
            float mr = m_s[(sty << 2) + i];
#pragma unroll
            for (int j = 0; j < 4; j++) {
                float e = __expf(sacc[i][j] - mr);
                pT[((stx << 2) + j) * 68 + (sty << 2) + i] = e;
            }
        }
        __syncthreads();

        // ---- row sum -> l update ----
        if (t < 64) {
            float s = 0.0f;
#pragma unroll 8
            for (int c = 0; c < TK; c++) s += pT[c * 68 + t];
            l_s[t] = l_s[t] * al_s[t] + s;
        }

        // ---- O = O*alpha + P @ V  (4x8 micro-tile) ----
#pragma unroll
        for (int i = 0; i < 4; i++) {
            float al = al_s[(oty << 2) + i];
#pragma unroll
            for (int j = 0; j < 8; j++) accO[i][j] *= al;
        }
#pragma unroll 2
        for (int kk = 0; kk < TK; kk++) {
            float4 pv = *(float4*)&pT[kk * 68 + (oty << 2)];
            float4 v0 = *(float4*)&vS[kk * 132 + (otx << 3)];
            float4 v1 = *(float4*)&vS[kk * 132 + (otx << 3) + 4];
            float pp[4] = {pv.x, pv.y, pv.z, pv.w};
            float vv[8] = {v0.x, v0.y, v0.z, v0.w, v1.x, v1.y, v1.z, v1.w};
#pragma unroll
            for (int i = 0; i < 4; i++)
#pragma unroll
                for (int j = 0; j < 8; j++)
                    accO[i][j] += pp[i] * vv[j];
        }
        __syncthreads();
    }

    // ---- epilogue: divide by l, write [b, q, h*128+c] ----
#pragma unroll
    for (int i = 0; i < 4; i++) {
        int r = (oty << 2) + i;
        float inv = 1.0f / l_s[r];
        size_t base = ((size_t)b * QL + r) * HID + h * HD + (otx << 3);
#pragma unroll
        for (int j = 0; j < 8; j++)
            out[base + j] = accO[i][j] * inv;
    }
}

// ---------------------------------------------------------------------------
extern "C" void kernel_launch(void* const* d_in, const int* in_sizes, int n_in,
                              void* d_out, int out_size)
{
    const float* hidden = (const float*)d_in[0];   // (4,64,4096)
    const float* target = (const float*)d_in[1];   // (4,4096,4096)
    const float* cosp   = (const float*)d_in[2];   // (4160,128)
    const float* sinp   = (const float*)d_in[3];   // (4160,128)
    const float* Wqkv   = (const float*)d_in[4];   // (4096,12288)
    const float* Wo     = (const float*)d_in[5];   // (4096,4096)
    const float* qnw    = (const float*)d_in[6];   // (128,)
    float* out = (float*)d_out;                    // (4,64,4096)

    float *qproj, *qrope, *attn;
    cudaGetSymbolAddress((void**)&qproj, g_qproj);
    cudaGetSymbolAddress((void**)&qrope, g_q);
    cudaGetSymbolAddress((void**)&attn,  g_attn);

    // 1) Q projection: only the first HID columns of Wqkv are ever used.
    dim3 gg(HID / 64, (BB * QL) / 64);   // (64, 4)
    gemm64_kernel<<<gg, 256>>>(hidden, Wqkv, qproj, BB * QL, HID, HID, 3 * HID);

    // 2) double RMSNorm + RoPE on Q
    qnorm_rope_kernel<<<BB * QL * NH, 128>>>(qproj, qnw, cosp, sinp, qrope);

    // 3) flash attention (fused K-rope; V = pre-rope raw data)
    size_t smem = (size_t)(2 * 128 * 68 + 64 * 132 + 64 * 68 + 3 * 64) * sizeof(float);
    cudaFuncSetAttribute(attn_kernel, cudaFuncAttributeMaxDynamicSharedMemorySize, (int)smem);
    dim3 ga(NH, BB);                     // (32, 4)
    attn_kernel<<<ga, 256, smem>>>(qrope, target, hidden, cosp, sinp, attn);

    // 4) output projection
    gemm64_kernel<<<gg, 256>>>(attn, Wo, out, BB * QL, HID, HID, HID);
}

// round 4
// speedup vs baseline: 1.5243x; 1.5243x over previous
#include <cuda_runtime.h>
#include <cstdint>
#include <math.h>

#define NH   32
#define HD   128
#define BB   4
#define QL   64
#define CTX  4096
#define HID  4096
#define TOTAL_KV (CTX + QL)
#define TKk  64
#define NTILE (TOTAL_KV / TKk)   // 65

__device__ float g_qproj[BB * QL * HID];
__device__ float g_q[BB * NH * QL * HD];
__device__ float g_attn[BB * QL * HID];

__device__ __forceinline__ uint32_t smem_u32(const void* p) {
    uint32_t a;
    asm("{ .reg .u64 t; cvta.to.shared.u64 t, %1; cvt.u32.u64 %0, t; }" : "=r"(a) : "l"(p));
    return a;
}
__device__ __forceinline__ void ldsm4(uint32_t* r, uint32_t a) {
    asm volatile("ldmatrix.sync.aligned.m8n8.x4.shared.b16 {%0,%1,%2,%3}, [%4];"
        : "=r"(r[0]), "=r"(r[1]), "=r"(r[2]), "=r"(r[3]) : "r"(a));
}
__device__ __forceinline__ void ldsm4t(uint32_t* r, uint32_t a) {
    asm volatile("ldmatrix.sync.aligned.m8n8.x4.trans.shared.b16 {%0,%1,%2,%3}, [%4];"
        : "=r"(r[0]), "=r"(r[1]), "=r"(r[2]), "=r"(r[3]) : "r"(a));
}
__device__ __forceinline__ void mma16816(float* c, const uint32_t* a, const uint32_t* b) {
    asm volatile(
        "mma.sync.aligned.m16n8k16.row.col.f32.bf16.bf16.f32 "
        "{%0,%1,%2,%3}, {%4,%5,%6,%7}, {%8,%9}, {%0,%1,%2,%3};"
        : "+f"(c[0]), "+f"(c[1]), "+f"(c[2]), "+f"(c[3])
        : "r"(a[0]), "r"(a[1]), "r"(a[2]), "r"(a[3]), "r"(b[0]), "r"(b[1]));
}
// split pair (e0,e1) into packed bf16x2 hi word + lo (residual) word
__device__ __forceinline__ void split_pack(float e0, float e1, uint32_t& hi, uint32_t& lo) {
    uint32_t h;
    asm("cvt.rn.bf16x2.f32 %0, %1, %2;" : "=r"(h) : "f"(e1), "f"(e0));
    float f0 = __uint_as_float(h << 16);
    float f1 = __uint_as_float(h & 0xffff0000u);
    uint32_t l;
    asm("cvt.rn.bf16x2.f32 %0, %1, %2;" : "=r"(l) : "f"(e1 - f1), "f"(e0 - f0));
    hi = h; lo = l;
}

// ===========================================================================
// bf16-split GEMM: C[256,N] = A[256,K] @ W[K,N] (row stride ldb)
// block 128m x 64n, BK=32, 256 thr, 8 warps (4m x 2n), warp 32x32
// ===========================================================================
#define AST 40
#define WST 72
#define ABYTES (128 * AST * 2)              // 10240
#define WBYTES (32 * WST * 2)               // 4608
#define STAGE  (2 * ABYTES + 2 * WBYTES)    // 29696
#define GSMEM  (2 * STAGE)

#define GEMM_LDG(c) do { \
  _Pragma("unroll") for (int q = 0; q < 4; q++) { int i = t + q * 256; \
    ra[q] = *(const float4*)(A + (size_t)(m0 + (i >> 3)) * K + (c) * 32 + (i & 7) * 4); } \
  _Pragma("unroll") for (int q = 0; q < 2; q++) { int i = t + q * 256; \
    rw[q] = *(const float4*)(W + (size_t)((c) * 32 + (i >> 4)) * ldb + n0 + (i & 15) * 4); } \
} while (0)

#define GEMM_STS(bufp) do { \
  _Pragma("unroll") for (int q = 0; q < 4; q++) { int i = t + q * 256; \
    int row = i >> 3, kc = (i & 7) * 4; uint32_t h0, l0, h1, l1; \
    split_pack(ra[q].x, ra[q].y, h0, l0); split_pack(ra[q].z, ra[q].w, h1, l1); \
    uint32_t off = (uint32_t)(row * AST + kc) * 2; \
    *(uint2*)((bufp) + off) = make_uint2(h0, h1); \
    *(uint2*)((bufp) + ABYTES + off) = make_uint2(l0, l1); } \
  _Pragma("unroll") for (int q = 0; q < 2; q++) { int i = t + q * 256; \
    int kr = i >> 4, nc = (i & 15) * 4; uint32_t h0, l0, h1, l1; \
    split_pack(rw[q].x, rw[q].y, h0, l0); split_pack(rw[q].z, rw[q].w, h1, l1); \
    uint32_t off = (uint32_t)(kr * WST + nc) * 2; \
    *(uint2*)((bufp) + 2 * ABYTES + off) = make_uint2(h0, h1); \
    *(uint2*)((bufp) + 2 * ABYTES + WBYTES + off) = make_uint2(l0, l1); } \
} while (0)

__global__ __launch_bounds__(256) void gemm_bf16s(
    const float* __restrict__ A, const float* __restrict__ W,
    float* __restrict__ C, int K, int N, int ldb)
{
    extern __shared__ __align__(16) char smc[];
    const uint32_t smb = smem_u32(smc);
    const int t = threadIdx.x, w = t >> 5, L = t & 31, g = L >> 3, r8 = L & 7;
    const int wm = w >> 1, wn = w & 1;
    const int m0 = blockIdx.y * 128, n0 = blockIdx.x * 64;
    const int NCH = K / 32;

    float4 ra[4]; float4 rw[2];
    float acc[2][4][4] = {};

    GEMM_LDG(0);
    GEMM_STS(smc);
    __syncthreads();
    if (NCH > 1) GEMM_LDG(1);

    for (int c = 0; c < NCH; c++) {
        const uint32_t sb = smb + (uint32_t)(c & 1) * STAGE;
#pragma unroll
        for (int ks = 0; ks < 2; ks++) {
            uint32_t ah[2][4], al[2][4], bh[4][2], bl[4][2];
#pragma unroll
            for (int mf = 0; mf < 2; mf++) {
                uint32_t ad = sb + (uint32_t)((wm * 32 + mf * 16 + (g & 1) * 8 + r8) * AST
                                              + ks * 16 + (g >> 1) * 8) * 2;
                ldsm4(ah[mf], ad);
                ldsm4(al[mf], ad + ABYTES);
            }
#pragma unroll
            for (int nt = 0; nt < 2; nt++) {
                int kk = ks * 16 + (L & 15);
                int nn = wn * 32 + nt * 16 + ((L >> 4) << 3);
                uint32_t bd = sb + 2 * ABYTES + (uint32_t)(kk * WST + nn) * 2;
                uint32_t r4[4];
                ldsm4t(r4, bd);
                bh[nt * 2][0] = r4[0]; bh[nt * 2][1] = r4[1];
                bh[nt * 2 + 1][0] = r4[2]; bh[nt * 2 + 1][1] = r4[3];
                ldsm4t(r4, bd + WBYTES);
                bl[nt * 2][0] = r4[0]; bl[nt * 2][1] = r4[1];
                bl[nt * 2 + 1][0] = r4[2]; bl[nt * 2 + 1][1] = r4[3];
            }
#pragma unroll
            for (int mf = 0; mf < 2; mf++)
#pragma unroll
                for (int nf = 0; nf < 4; nf++) {
                    mma16816(acc[mf][nf], ah[mf], bh[nf]);
                    mma16816(acc[mf][nf], ah[mf], bl[nf]);
                    mma16816(acc[mf][nf], al[mf], bh[nf]);
                }
        }
        if (c + 1 < NCH) {
            GEMM_STS(smc + ((c + 1) & 1) * STAGE);
            if (c + 2 < NCH) GEMM_LDG(c + 2);
        }
        __syncthreads();
    }

#pragma unroll
    for (int mf = 0; mf < 2; mf++)
#pragma unroll
        for (int nf = 0; nf < 4; nf++) {
            int col = n0 + wn * 32 + nf * 8 + (L & 3) * 2;
            int r0 = m0 + wm * 32 + mf * 16 + (L >> 2);
            *(float2*)&C[(size_t)r0 * N + col] = make_float2(acc[mf][nf][0], acc[mf][nf][1]);
            *(float2*)&C[(size_t)(r0 + 8) * N + col] = make_float2(acc[mf][nf][2], acc[mf][nf][3]);
        }
}

// ---------------------------------------------------------------------------
// Fused double-RMSNorm + RoPE on Q.
// ---------------------------------------------------------------------------
__global__ __launch_bounds__(128) void qnorm_rope_kernel(
    const float* __restrict__ qproj, const float* __restrict__ w,
    const float* __restrict__ cosp, const float* __restrict__ sinp,
    float* __restrict__ qout)
{
    const int blk = blockIdx.x;
    const int h = blk & 31;
    const int m = blk >> 5;
    const int b = m >> 6, q = m & 63;
    const int d = threadIdx.x;

    __shared__ float red[4];
    __shared__ float zbuf[128];

    float x = qproj[(size_t)m * HID + h * HD + d];
    float v = x * x;
#pragma unroll
    for (int o = 16; o > 0; o >>= 1) v += __shfl_down_sync(0xffffffffu, v, o);
    if ((d & 31) == 0) red[d >> 5] = v;
    __syncthreads();
    float mean1 = (red[0] + red[1] + red[2] + red[3]) * (1.0f / 128.0f);
    float y = x * rsqrtf(mean1 + 1e-6f) * w[d];
    __syncthreads();
    v = y * y;
#pragma unroll
    for (int o = 16; o > 0; o >>= 1) v += __shfl_down_sync(0xffffffffu, v, o);
    if ((d & 31) == 0) red[d >> 5] = v;
    __syncthreads();
    float mean2 = (red[0] + red[1] + red[2] + red[3]) * (1.0f / 128.0f);
    float z = y * rsqrtf(mean2 + 1e-6f) * w[d];
    zbuf[d] = z;
    __syncthreads();
    const int pos = CTX + q;
    float rot = (d < 64) ? -zbuf[d + 64] : zbuf[d - 64];
    qout[(((size_t)(b * NH + h) * QL) + q) * HD + d] =
        z * cosp[(size_t)pos * HD + d] + rot * sinp[(size_t)pos * HD + d];
}

// ===========================================================================
// Flash attention, bf16-split mma. One block per (b,h). 256 threads.
// V = raw concat tile (pre-RoPE); K = RoPE(raw) stored [d][pos].
// ===========================================================================
#define VRAW 0                       // f32 [64][132]  33792
#define QHI  33792                   // [64][136] bf16 17408
#define QLO  51200
#define KHI  68608                   // [128][72] 18432
#define KLO  87040
#define VHI  105472                  // [64][136] 17408
#define VLO  122880
#define PHI  140288                  // [64][72] 9216
#define PLO  149504
#define STAT 158720                  // m(64f) l(+256B) al(+512B) rmax(+768B) rsum(+1280B)
#define ATT_SMEM 160512

__global__ __launch_bounds__(256) void attn_kernel(
    const float* __restrict__ qin, const float* __restrict__ target,
    const float* __restrict__ hidden, const float* __restrict__ cosp,
    const float* __restrict__ sinp, float* __restrict__ out)
{
    extern __shared__ __align__(16) char smc[];
    const uint32_t smb = smem_u32(smc);
    float* vraw = (float*)(smc + VRAW);
    float* m_s  = (float*)(smc + STAT);
    float* l_s  = m_s + 64;
    float* al_s = l_s + 64;
    float* rmax = al_s + 64;   // [2][64]
    float* rsum = rmax + 128;  // [2][64]

    const int h = blockIdx.x, b = blockIdx.y;
    const int t = threadIdx.x, w = t >> 5, L = t & 31, g = L >> 3, r8 = L & 7;
    const int wm = w >> 1, wn = w & 1;   // S roles
    const int vd = w & 1;                // PV d-half (same wm for m)
    const float scale = 0.08838834764831845f;

    // Q load + split (scaled)
    const float* qb = qin + ((size_t)(b * NH + h) * QL) * HD;
#pragma unroll
    for (int i = 0; i < 16; i++) {
        int idx = t + i * 256;            // 4096 pairs
        int row = idx >> 6, d0 = (idx & 63) * 2;
        float e0 = qb[row * HD + d0] * scale;
        float e1 = qb[row * HD + d0 + 1] * scale;
        uint32_t hw, lw; split_pack(e0, e1, hw, lw);
        uint32_t off = (uint32_t)(row * 136 + d0) * 2;
        *(uint32_t*)(smc + QHI + off) = hw;
        *(uint32_t*)(smc + QLO + off) = lw;
    }
    if (t < 64) { m_s[t] = -1e30f; l_s[t] = 0.0f; }

    float oacc[8][4] = {};

    for (int tile = 0; tile < NTILE; tile++) {
        const int p0 = tile * TKk;
        // (a) raw tile load
#pragma unroll
        for (int i = 0; i < 8; i++) {
            int idx = t + i * 256;
            int row = idx >> 5, c4 = (idx & 31) * 4;
            int p = p0 + row;
            const float* src = (p < CTX)
                ? (target + ((size_t)b * CTX + p) * HID + h * HD)
                : (hidden + ((size_t)b * QL + (p - CTX)) * HID + h * HD);
            *(float4*)&vraw[row * 132 + c4] = *(const float4*)(src + c4);
        }
        __syncthreads();
        // (b) V split [pos][d]
#pragma unroll
        for (int i = 0; i < 16; i++) {
            int idx = t + i * 256;
            int pos = idx >> 6, d0 = (idx & 63) * 2;
            uint32_t hw, lw;
            split_pack(vraw[pos * 132 + d0], vraw[pos * 132 + d0 + 1], hw, lw);
            uint32_t off = (uint32_t)(pos * 136 + d0) * 2;
            *(uint32_t*)(smc + VHI + off) = hw;
            *(uint32_t*)(smc + VLO + off) = lw;
        }
        //     K = rope(raw), split, [d][pos]
#pragma unroll
        for (int i = 0; i < 16; i++) {
            int idx = t + i * 256;
            int d = idx >> 5, i0 = (idx & 31) * 2;
            float e[2];
#pragma unroll
            for (int u = 0; u < 2; u++) {
                int ii = i0 + u, p = p0 + ii;
                float x = vraw[ii * 132 + d];
                float rot = (d < 64) ? -vraw[ii * 132 + d + 64] : vraw[ii * 132 + d - 64];
                e[u] = x * cosp[(size_t)p * HD + d] + rot * sinp[(size_t)p * HD + d];
            }
            uint32_t hw, lw; split_pack(e[0], e[1], hw, lw);
            uint32_t off = (uint32_t)(d * 72 + i0) * 2;
            *(uint32_t*)(smc + KHI + off) = hw;
            *(uint32_t*)(smc + KLO + off) = lw;
        }
        __syncthreads();
        // (c) S = Q K^T : warp (wm m16, wn 32-keys)
        float sacc[4][4] = {};
#pragma unroll
        for (int ds = 0; ds < 8; ds++) {
            uint32_t ah[4], al[4], bh[4][2], bl[4][2];
            uint32_t ad = smb + QHI + (uint32_t)((wm * 16 + (g & 1) * 8 + r8) * 136
                                                 + ds * 16 + (g >> 1) * 8) * 2;
            ldsm4(ah, ad);
            ldsm4(al, ad + (QLO - QHI));
#pragma unroll
            for (int nt = 0; nt < 2; nt++) {
                int kk = ds * 16 + (L & 15);
                int nn = wn * 32 + nt * 16 + ((L >> 4) << 3);
                uint32_t bd = smb + KHI + (uint32_t)(kk * 72 + nn) * 2;
                uint32_t r4[4];
                ldsm4t(r4, bd);
                bh[nt * 2][0] = r4[0]; bh[nt * 2][1] = r4[1];
                bh[nt * 2 + 1][0] = r4[2]; bh[nt * 2 + 1][1] = r4[3];
                ldsm4t(r4, bd + (KLO - KHI));
                bl[nt * 2][0] = r4[0]; bl[nt * 2][1] = r4[1];
                bl[nt * 2 + 1][0] = r4[2]; bl[nt * 2 + 1][1] = r4[3];
            }
#pragma unroll
            for (int nf = 0; nf < 4; nf++) {
                mma16816(sacc[nf], ah, bh[nf]);
                mma16816(sacc[nf], ah, bl[nf]);
                mma16816(sacc[nf], al, bh[nf]);
            }
        }
        // (d) per-row max over this warp's 32 keys
        {
            float mx0 = -1e30f, mx1 = -1e30f;
#pragma unroll
            for (int nf = 0; nf < 4; nf++) {
                mx0 = fmaxf(mx0, fmaxf(sacc[nf][0], sacc[nf][1]));
                mx1 = fmaxf(mx1, fmaxf(sacc[nf][2], sacc[nf][3]));
            }
            mx0 = fmaxf(mx0, __shfl_xor_sync(0xffffffffu, mx0, 1));
            mx0 = fmaxf(mx0, __shfl_xor_sync(0xffffffffu, mx0, 2));
            mx1 = fmaxf(mx1, __shfl_xor_sync(0xffffffffu, mx1, 1));
            mx1 = fmaxf(mx1, __shfl_xor_sync(0xffffffffu, mx1, 2));
            if ((L & 3) == 0) {
                rmax[wn * 64 + wm * 16 + (L >> 2)] = mx0;
                rmax[wn * 64 + wm * 16 + (L >> 2) + 8] = mx1;
            }
        }
        __syncthreads();
        // (e) m/alpha update
        if (t < 64) {
            float tm = fmaxf(rmax[t], rmax[64 + t]);
            float mold = m_s[t];
            float mnew = fmaxf(mold, tm);
            al_s[t] = __expf(mold - mnew);
            m_s[t] = mnew;
        }
        __syncthreads();
        // (f) exponentiate, split-store P, row sums
        {
            int r0 = wm * 16 + (L >> 2), r1 = r0 + 8;
            float mr0 = m_s[r0], mr1 = m_s[r1];
            float s0 = 0.f, s1 = 0.f;
#pragma unroll
            for (int nf = 0; nf < 4; nf++) {
                float e0 = __expf(sacc[nf][0] - mr0);
                float e1 = __expf(sacc[nf][1] - mr0);
                float e2 = __expf(sacc[nf][2] - mr1);
                float e3 = __expf(sacc[nf][3] - mr1);
                s0 += e0 + e1; s1 += e2 + e3;
                uint32_t hw, lw;
                int col = wn * 32 + nf * 8 + (L & 3) * 2;
                split_pack(e0, e1, hw, lw);
                *(uint32_t*)(smc + PHI + (uint32_t)(r0 * 72 + col) * 2) = hw;
                *(uint32_t*)(smc + PLO + (uint32_t)(r0 * 72 + col) * 2) = lw;
                split_pack(e2, e3, hw, lw);
                *(uint32_t*)(smc + PHI + (uint32_t)(r1 * 72 + col) * 2) = hw;
                *(uint32_t*)(smc + PLO + (uint32_t)(r1 * 72 + col) * 2) = lw;
            }
            s0 += __shfl_xor_sync(0xffffffffu, s0, 1);
            s0 += __shfl_xor_sync(0xffffffffu, s0, 2);
            s1 += __shfl_xor_sync(0xffffffffu, s1, 1);
            s1 += __shfl_xor_sync(0xffffffffu, s1, 2);
            if ((L & 3) == 0) { rsum[wn * 64 + r0] = s0; rsum[wn * 64 + r1] = s1; }
        }
        __syncthreads();
        // (g) l update
        if (t < 64) l_s[t] = l_s[t] * al_s[t] + rsum[t] + rsum[64 + t];
        // (h) O = O*alpha + P V : warp (wm m16, vd d-half64)
        {
            int r0 = wm * 16 + (L >> 2);
            float a0 = al_s[r0], a1 = al_s[r0 + 8];
#pragma unroll
            for (int nf = 0; nf < 8; nf++) {
                oacc[nf][0] *= a0; oacc[nf][1] *= a0;
                oacc[nf][2] *= a1; oacc[nf][3] *= a1;
            }
#pragma unroll
            for (int ks = 0; ks < 4; ks++) {
                uint32_t ph[4], pl[4], vh[8][2], vl[8][2];
                uint32_t ad = smb + PHI + (uint32_t)((wm * 16 + (g & 1) * 8 + r8) * 72
                                                     + ks * 16 + (g >> 1) * 8) * 2;
                ldsm4(ph, ad);
                ldsm4(pl, ad + (PLO - PHI));
#pragma unroll
                for (int nt = 0; nt < 4; nt++) {
                    int kk = ks * 16 + (L & 15);
                    int nn = vd * 64 + nt * 16 + ((L >> 4) << 3);
                    uint32_t bd = smb + VHI + (uint32_t)(kk * 136 + nn) * 2;
                    uint32_t r4[4];
                    ldsm4t(r4, bd);
                    vh[nt * 2][0] = r4[0]; vh[nt * 2][1] = r4[1];
                    vh[nt * 2 + 1][0] = r4[2]; vh[nt * 2 + 1][1] = r4[3];
                    ldsm4t(r4, bd + (VLO - VHI));
                    vl[nt * 2][0] = r4[0]; vl[nt * 2][1] = r4[1];
                    vl[nt * 2 + 1][0] = r4[2]; vl[nt * 2 + 1][1] = r4[3];
                }
#pragma unroll
                for (int nf = 0; nf < 8; nf++) {
                    mma16816(oacc[nf], ph, vh[nf]);
                    mma16816(oacc[nf], ph, vl[nf]);
                    mma16816(oacc[nf], pl, vh[nf]);
                }
            }
        }
        __syncthreads();
    }

    // epilogue
    {
        int r0 = wm * 16 + (L >> 2), r1 = r0 + 8;
        float inv0 = 1.0f / l_s[r0], inv1 = 1.0f / l_s[r1];
#pragma unroll
        for (int nf = 0; nf < 8; nf++) {
            int d = vd * 64 + nf * 8 + (L & 3) * 2;
            size_t base0 = ((size_t)b * QL + r0) * HID + h * HD + d;
            size_t base1 = ((size_t)b * QL + r1) * HID + h * HD + d;
            *(float2*)&out[base0] = make_float2(oacc[nf][0] * inv0, oacc[nf][1] * inv0);
            *(float2*)&out[base1] = make_float2(oacc[nf][2] * inv1, oacc[nf][3] * inv1);
        }
    }
}

// ---------------------------------------------------------------------------
extern "C" void kernel_launch(void* const* d_in, const int* in_sizes, int n_in,
                              void* d_out, int out_size)
{
    const float* hidden = (const float*)d_in[0];
    const float* target = (const float*)d_in[1];
    const float* cosp   = (const float*)d_in[2];
    const float* sinp   = (const float*)d_in[3];
    const float* Wqkv   = (const float*)d_in[4];
    const float* Wo     = (const float*)d_in[5];
    const float* qnw    = (const float*)d_in[6];
    float* out = (float*)d_out;

    float *qproj, *qrope, *attn;
    cudaGetSymbolAddress((void**)&qproj, g_qproj);
    cudaGetSymbolAddress((void**)&qrope, g_q);
    cudaGetSymbolAddress((void**)&attn,  g_attn);

    cudaFuncSetAttribute(gemm_bf16s, cudaFuncAttributeMaxDynamicSharedMemorySize, GSMEM);
    cudaFuncSetAttribute(attn_kernel, cudaFuncAttributeMaxDynamicSharedMemorySize, ATT_SMEM);

    dim3 gg(HID / 64, (BB * QL) / 128);  // (64, 2)
    gemm_bf16s<<<gg, 256, GSMEM>>>(hidden, Wqkv, qproj, HID, HID, 3 * HID);

    qnorm_rope_kernel<<<BB * QL * NH, 128>>>(qproj, qnw, cosp, sinp, qrope);

    dim3 ga(NH, BB);
    attn_kernel<<<ga, 256, ATT_SMEM>>>(qrope, target, hidden, cosp, sinp, attn);

    gemm_bf16s<<<gg, 256, GSMEM>>>(attn, Wo, out, HID, HID, HID);
}

// round 5
// speedup vs baseline: 2.9734x; 1.9507x over previous
#include <cuda_runtime.h>
#include <cstdint>
#include <math.h>

#define NH   32
#define HD   128
#define BB   4
#define QL   64
#define CTX  4096
#define HID  4096
#define TOTAL_KV (CTX + QL)
#define NTILE (TOTAL_KV / 64)    // 65

__device__ float g_qproj[BB * QL * HID];
__device__ float g_q[BB * NH * QL * HD];
__device__ float g_attn[BB * QL * HID];

__device__ __forceinline__ uint32_t smem_u32(const void* p) {
    uint32_t a;
    asm("{ .reg .u64 t; cvta.to.shared.u64 t, %1; cvt.u32.u64 %0, t; }" : "=r"(a) : "l"(p));
    return a;
}
__device__ __forceinline__ void ldsm4(uint32_t* r, uint32_t a) {
    asm volatile("ldmatrix.sync.aligned.m8n8.x4.shared.b16 {%0,%1,%2,%3}, [%4];"
        : "=r"(r[0]), "=r"(r[1]), "=r"(r[2]), "=r"(r[3]) : "r"(a));
}
__device__ __forceinline__ void ldsm4t(uint32_t* r, uint32_t a) {
    asm volatile("ldmatrix.sync.aligned.m8n8.x4.trans.shared.b16 {%0,%1,%2,%3}, [%4];"
        : "=r"(r[0]), "=r"(r[1]), "=r"(r[2]), "=r"(r[3]) : "r"(a));
}
__device__ __forceinline__ void mma16816(float* c, const uint32_t* a, const uint32_t* b) {
    asm volatile(
        "mma.sync.aligned.m16n8k16.row.col.f32.bf16.bf16.f32 "
        "{%0,%1,%2,%3}, {%4,%5,%6,%7}, {%8,%9}, {%0,%1,%2,%3};"
        : "+f"(c[0]), "+f"(c[1]), "+f"(c[2]), "+f"(c[3])
        : "r"(a[0]), "r"(a[1]), "r"(a[2]), "r"(a[3]), "r"(b[0]), "r"(b[1]));
}
__device__ __forceinline__ void split_pack(float e0, float e1, uint32_t& hi, uint32_t& lo) {
    uint32_t h;
    asm("cvt.rn.bf16x2.f32 %0, %1, %2;" : "=r"(h) : "f"(e1), "f"(e0));
    float f0 = __uint_as_float(h << 16);
    float f1 = __uint_as_float(h & 0xffff0000u);
    uint32_t l;
    asm("cvt.rn.bf16x2.f32 %0, %1, %2;" : "=r"(l) : "f"(e1 - f1), "f"(e0 - f0));
    hi = h; lo = l;
}
#define CPA16(d, s) asm volatile("cp.async.cg.shared.global [%0], [%1], 16;" :: "r"(d), "l"(s))
#define CPC()  asm volatile("cp.async.commit_group;" ::: "memory")
#define CPW1() asm volatile("cp.async.wait_group 1;" ::: "memory")

// ===========================================================================
// bf16-split GEMM (unchanged from R4): C[256,N] = A[256,K] @ W[K,N]
// ===========================================================================
#define AST 40
#define WST 72
#define ABYTES (128 * AST * 2)
#define WBYTES (32 * WST * 2)
#define STAGE  (2 * ABYTES + 2 * WBYTES)
#define GSMEM  (2 * STAGE)

#define GEMM_LDG(c) do { \
  _Pragma("unroll") for (int q = 0; q < 4; q++) { int i = t + q * 256; \
    ra[q] = *(const float4*)(A + (size_t)(m0 + (i >> 3)) * K + (c) * 32 + (i & 7) * 4); } \
  _Pragma("unroll") for (int q = 0; q < 2; q++) { int i = t + q * 256; \
    rw[q] = *(const float4*)(W + (size_t)((c) * 32 + (i >> 4)) * ldb + n0 + (i & 15) * 4); } \
} while (0)

#define GEMM_STS(bufp) do { \
  _Pragma("unroll") for (int q = 0; q < 4; q++) { int i = t + q * 256; \
    int row = i >> 3, kc = (i & 7) * 4; uint32_t h0, l0, h1, l1; \
    split_pack(ra[q].x, ra[q].y, h0, l0); split_pack(ra[q].z, ra[q].w, h1, l1); \
    uint32_t off = (uint32_t)(row * AST + kc) * 2; \
    *(uint2*)((bufp) + off) = make_uint2(h0, h1); \
    *(uint2*)((bufp) + ABYTES + off) = make_uint2(l0, l1); } \
  _Pragma("unroll") for (int q = 0; q < 2; q++) { int i = t + q * 256; \
    int kr = i >> 4, nc = (i & 15) * 4; uint32_t h0, l0, h1, l1; \
    split_pack(rw[q].x, rw[q].y, h0, l0); split_pack(rw[q].z, rw[q].w, h1, l1); \
    uint32_t off = (uint32_t)(kr * WST + nc) * 2; \
    *(uint2*)((bufp) + 2 * ABYTES + off) = make_uint2(h0, h1); \
    *(uint2*)((bufp) + 2 * ABYTES + WBYTES + off) = make_uint2(l0, l1); } \
} while (0)

__global__ __launch_bounds__(256) void gemm_bf16s(
    const float* __restrict__ A, const float* __restrict__ W,
    float* __restrict__ C, int K, int N, int ldb)
{
    extern __shared__ __align__(16) char smc[];
    const uint32_t smb = smem_u32(smc);
    const int t = threadIdx.x, w = t >> 5, L = t & 31, g = L >> 3, r8 = L & 7;
    const int wm = w >> 1, wn = w & 1;
    const int m0 = blockIdx.y * 128, n0 = blockIdx.x * 64;
    const int NCH = K / 32;

    float4 ra[4]; float4 rw[2];
    float acc[2][4][4] = {};

    GEMM_LDG(0);
    GEMM_STS(smc);
    __syncthreads();
    if (NCH > 1) GEMM_LDG(1);

    for (int c = 0; c < NCH; c++) {
        const uint32_t sb = smb + (uint32_t)(c & 1) * STAGE;
#pragma unroll
        for (int ks = 0; ks < 2; ks++) {
            uint32_t ah[2][4], al[2][4], bh[4][2], bl[4][2];
#pragma unroll
            for (int mf = 0; mf < 2; mf++) {
                uint32_t ad = sb + (uint32_t)((wm * 32 + mf * 16 + (g & 1) * 8 + r8) * AST
                                              + ks * 16 + (g >> 1) * 8) * 2;
                ldsm4(ah[mf], ad);
                ldsm4(al[mf], ad + ABYTES);
            }
#pragma unroll
            for (int nt = 0; nt < 2; nt++) {
                int kk = ks * 16 + (L & 15);
                int nn = wn * 32 + nt * 16 + ((L >> 4) << 3);
                uint32_t bd = sb + 2 * ABYTES + (uint32_t)(kk * WST + nn) * 2;
                uint32_t r4[4];
                ldsm4t(r4, bd);
                bh[nt * 2][0] = r4[0]; bh[nt * 2][1] = r4[1];
                bh[nt * 2 + 1][0] = r4[2]; bh[nt * 2 + 1][1] = r4[3];
                ldsm4t(r4, bd + WBYTES);
                bl[nt * 2][0] = r4[0]; bl[nt * 2][1] = r4[1];
                bl[nt * 2 + 1][0] = r4[2]; bl[nt * 2 + 1][1] = r4[3];
            }
#pragma unroll
            for (int mf = 0; mf < 2; mf++)
#pragma unroll
                for (int nf = 0; nf < 4; nf++) {
                    mma16816(acc[mf][nf], ah[mf], bh[nf]);
                    mma16816(acc[mf][nf], ah[mf], bl[nf]);
                    mma16816(acc[mf][nf], al[mf], bh[nf]);
                }
        }
        if (c + 1 < NCH) {
            GEMM_STS(smc + ((c + 1) & 1) * STAGE);
            if (c + 2 < NCH) GEMM_LDG(c + 2);
        }
        __syncthreads();
    }

#pragma unroll
    for (int mf = 0; mf < 2; mf++)
#pragma unroll
        for (int nf = 0; nf < 4; nf++) {
            int col = n0 + wn * 32 + nf * 8 + (L & 3) * 2;
            int r0 = m0 + wm * 32 + mf * 16 + (L >> 2);
            *(float2*)&C[(size_t)r0 * N + col] = make_float2(acc[mf][nf][0], acc[mf][nf][1]);
            *(float2*)&C[(size_t)(r0 + 8) * N + col] = make_float2(acc[mf][nf][2], acc[mf][nf][3]);
        }
}

// ---------------------------------------------------------------------------
// Fused double-RMSNorm + RoPE on Q (unchanged).
// ---------------------------------------------------------------------------
__global__ __launch_bounds__(128) void qnorm_rope_kernel(
    const float* __restrict__ qproj, const float* __restrict__ w,
    const float* __restrict__ cosp, const float* __restrict__ sinp,
    float* __restrict__ qout)
{
    const int blk = blockIdx.x;
    const int h = blk & 31;
    const int m = blk >> 5;
    const int b = m >> 6, q = m & 63;
    const int d = threadIdx.x;

    __shared__ float red[4];
    __shared__ float zbuf[128];

    float x = qproj[(size_t)m * HID + h * HD + d];
    float v = x * x;
#pragma unroll
    for (int o = 16; o > 0; o >>= 1) v += __shfl_down_sync(0xffffffffu, v, o);
    if ((d & 31) == 0) red[d >> 5] = v;
    __syncthreads();
    float mean1 = (red[0] + red[1] + red[2] + red[3]) * (1.0f / 128.0f);
    float y = x * rsqrtf(mean1 + 1e-6f) * w[d];
    __syncthreads();
    v = y * y;
#pragma unroll
    for (int o = 16; o > 0; o >>= 1) v += __shfl_down_sync(0xffffffffu, v, o);
    if ((d & 31) == 0) red[d >> 5] = v;
    __syncthreads();
    float mean2 = (red[0] + red[1] + red[2] + red[3]) * (1.0f / 128.0f);
    float z = y * rsqrtf(mean2 + 1e-6f) * w[d];
    zbuf[d] = z;
    __syncthreads();
    const int pos = CTX + q;
    float rot = (d < 64) ? -zbuf[d + 64] : zbuf[d - 64];
    qout[(((size_t)(b * NH + h) * QL) + q) * HD + d] =
        z * cosp[(size_t)pos * HD + d] + rot * sinp[(size_t)pos * HD + d];
}

// ===========================================================================
// Flash attention v2: 512 threads, cp.async double-buffered, pipelined.
// ===========================================================================
#define RAW0 0
#define RAW1 32768
#define KHOF 65536            // KH(s) = KHOF + s*36864 ; KL = KH + 18432
#define VHOF 139264           // VH(s) = VHOF + s*34816 ; VL = VH + 17408
#define PHOF 208896
#define PLOF 218112
#define STATOF 227328
#define ATT_SMEM 230144

__global__ __launch_bounds__(512, 1) void attn_kernel(
    const float* __restrict__ qin, const float* __restrict__ target,
    const float* __restrict__ hidden, const float* __restrict__ cosp,
    const float* __restrict__ sinp, float* __restrict__ out)
{
    extern __shared__ __align__(16) char smc[];
    const uint32_t smb = smem_u32(smc);
    float* m_s  = (float*)(smc + STATOF);
    float* l_s  = (float*)(smc + STATOF + 256);
    float* al_s = (float*)(smc + STATOF + 512);
    float* rmax = (float*)(smc + STATOF + 768);    // [4][64]
    float* rsum = (float*)(smc + STATOF + 1792);   // [4][64]

    const int h = blockIdx.x, b = blockIdx.y;
    const int t = threadIdx.x, w = t >> 5, L = t & 31, g = L >> 3, r8 = L & 7;
    const int wq = w >> 2, wk = w & 3;
    const float scale = 0.08838834764831845f;

    // ---- stage Q (hi/lo) through raw area, hoist fragments to registers ----
    const float* qb = qin + ((size_t)(b * NH + h) * QL) * HD;
#pragma unroll
    for (int i = 0; i < 8; i++) {
        int idx = t + i * 512, row = idx >> 6, d0 = (idx & 63) * 2;
        float e0 = qb[row * HD + d0] * scale, e1 = qb[row * HD + d0 + 1] * scale;
        uint32_t hw, lw; split_pack(e0, e1, hw, lw);
        *(uint32_t*)(smc + (uint32_t)(row * 136 + d0) * 2) = hw;
        *(uint32_t*)(smc + 17408 + (uint32_t)(row * 136 + d0) * 2) = lw;
    }
    if (t < 64) { m_s[t] = -1e30f; l_s[t] = 0.0f; }
    __syncthreads();
    uint32_t qhf[8][4], qlf[8][4];
#pragma unroll
    for (int ds = 0; ds < 8; ds++) {
        uint32_t ad = smb + (uint32_t)((wq * 16 + (g & 1) * 8 + r8) * 136
                                       + ds * 16 + (g >> 1) * 8) * 2;
        ldsm4(qhf[ds], ad);
        ldsm4(qlf[ds], ad + 17408);
    }
    __syncthreads();

    auto cp_tile = [&](int tn, uint32_t dstoff) {
        const int p0 = tn * 64;
#pragma unroll
        for (int q = 0; q < 4; q++) {
            int idx = t + q * 512, row = idx >> 5, c16 = idx & 31;
            int p = p0 + row;
            const float* src = (p < CTX)
                ? (target + ((size_t)b * CTX + p) * HID + h * HD + c16 * 4)
                : (hidden + ((size_t)b * QL + (p - CTX)) * HID + h * HD + c16 * 4);
            CPA16(smb + dstoff + (uint32_t)(row * 512 + c16 * 16), src);
        }
    };
    auto rope_split = [&](int tn, uint32_t rawoff, int s) {
        const float* rawf = (const float*)(smc + rawoff);
        const int p0 = tn * 64;
        const uint32_t kh = KHOF + (uint32_t)s * 36864;
        const uint32_t vh = VHOF + (uint32_t)s * 34816;
#pragma unroll
        for (int i = 0; i < 8; i++) {
            int idx = t + i * 512, pos = idx >> 6, d0 = (idx & 63) * 2;
            float2 xv = *(const float2*)(rawf + pos * 128 + d0);
            uint32_t hw, lw; split_pack(xv.x, xv.y, hw, lw);
            uint32_t voff = (uint32_t)(pos * 136 + d0) * 2;
            *(uint32_t*)(smc + vh + voff) = hw;
            *(uint32_t*)(smc + vh + 17408 + voff) = lw;
            float2 xr = (d0 < 64) ? *(const float2*)(rawf + pos * 128 + d0 + 64)
                                  : *(const float2*)(rawf + pos * 128 + d0 - 64);
            float rr0 = (d0 < 64) ? -xr.x : xr.x;
            float rr1 = (d0 < 64) ? -xr.y : xr.y;
            int p = p0 + pos;
            float2 cv = *(const float2*)(cosp + (size_t)p * HD + d0);
            float2 sv = *(const float2*)(sinp + (size_t)p * HD + d0);
            float e0 = xv.x * cv.x + rr0 * sv.x;
            float e1 = xv.y * cv.y + rr1 * sv.y;
            split_pack(e0, e1, hw, lw);
            *(uint16_t*)(smc + kh + (uint32_t)(d0 * 72 + pos) * 2) = (uint16_t)hw;
            *(uint16_t*)(smc + kh + (uint32_t)((d0 + 1) * 72 + pos) * 2) = (uint16_t)(hw >> 16);
            *(uint16_t*)(smc + kh + 18432 + (uint32_t)(d0 * 72 + pos) * 2) = (uint16_t)lw;
            *(uint16_t*)(smc + kh + 18432 + (uint32_t)((d0 + 1) * 72 + pos) * 2) = (uint16_t)(lw >> 16);
        }
    };

    // prologue: prefetch tiles 0,1; build K/V for tile 0
    cp_tile(0, RAW0); CPC();
    cp_tile(1, RAW1); CPC();
    CPW1();
    __syncthreads();
    rope_split(0, RAW0, 0);
    __syncthreads();

    float oacc[4][4] = {};
    const int r0 = wq * 16 + (L >> 2), r1 = r0 + 8;

    for (int tile = 0; tile < NTILE; tile++) {
        const int s = tile & 1;
        if (tile + 2 < NTILE) cp_tile(tile + 2, s ? RAW1 : RAW0);
        CPC();

        // ---- S = Q K^T ----
        const uint32_t kh = KHOF + (uint32_t)s * 36864;
        float sacc[2][4] = {};
#pragma unroll
        for (int ds = 0; ds < 8; ds++) {
            uint32_t bd = smb + kh + (uint32_t)((ds * 16 + (L & 15)) * 72
                                                + wk * 16 + (L >> 4) * 8) * 2;
            uint32_t bh4[4], bl4[4];
            ldsm4t(bh4, bd);
            ldsm4t(bl4, bd + 18432);
            mma16816(sacc[0], qhf[ds], bh4);
            mma16816(sacc[0], qhf[ds], bl4);
            mma16816(sacc[0], qlf[ds], bh4);
            mma16816(sacc[1], qhf[ds], bh4 + 2);
            mma16816(sacc[1], qhf[ds], bl4 + 2);
            mma16816(sacc[1], qlf[ds], bh4 + 2);
        }
        // warp-local row max over this warp's 16 keys
        float mx0 = fmaxf(fmaxf(sacc[0][0], sacc[0][1]), fmaxf(sacc[1][0], sacc[1][1]));
        float mx1 = fmaxf(fmaxf(sacc[0][2], sacc[0][3]), fmaxf(sacc[1][2], sacc[1][3]));
        mx0 = fmaxf(mx0, __shfl_xor_sync(0xffffffffu, mx0, 1));
        mx0 = fmaxf(mx0, __shfl_xor_sync(0xffffffffu, mx0, 2));
        mx1 = fmaxf(mx1, __shfl_xor_sync(0xffffffffu, mx1, 1));
        mx1 = fmaxf(mx1, __shfl_xor_sync(0xffffffffu, mx1, 2));
        if ((L & 3) == 0) { rmax[wk * 64 + r0] = mx0; rmax[wk * 64 + r1] = mx1; }
        __syncthreads();
        if (t < 64) {
            float tm = fmaxf(fmaxf(rmax[t], rmax[64 + t]), fmaxf(rmax[128 + t], rmax[192 + t]));
            float mold = m_s[t], mnew = fmaxf(mold, tm);
            al_s[t] = __expf(mold - mnew);
            m_s[t] = mnew;
        }
        __syncthreads();
        // ---- exp, split-store P, row sums ----
        {
            float mr0 = m_s[r0], mr1 = m_s[r1];
            float s0 = 0.f, s1 = 0.f;
#pragma unroll
            for (int nf = 0; nf < 2; nf++) {
                float e0 = __expf(sacc[nf][0] - mr0), e1 = __expf(sacc[nf][1] - mr0);
                float e2 = __expf(sacc[nf][2] - mr1), e3 = __expf(sacc[nf][3] - mr1);
                s0 += e0 + e1; s1 += e2 + e3;
                int col = wk * 16 + nf * 8 + (L & 3) * 2;
                uint32_t hw, lw;
                split_pack(e0, e1, hw, lw);
                *(uint32_t*)(smc + PHOF + (uint32_t)(r0 * 72 + col) * 2) = hw;
                *(uint32_t*)(smc + PLOF + (uint32_t)(r0 * 72 + col) * 2) = lw;
                split_pack(e2, e3, hw, lw);
                *(uint32_t*)(smc + PHOF + (uint32_t)(r1 * 72 + col) * 2) = hw;
                *(uint32_t*)(smc + PLOF + (uint32_t)(r1 * 72 + col) * 2) = lw;
            }
            s0 += __shfl_xor_sync(0xffffffffu, s0, 1);
            s0 += __shfl_xor_sync(0xffffffffu, s0, 2);
            s1 += __shfl_xor_sync(0xffffffffu, s1, 1);
            s1 += __shfl_xor_sync(0xffffffffu, s1, 2);
            if ((L & 3) == 0) { rsum[wk * 64 + r0] = s0; rsum[wk * 64 + r1] = s1; }
        }
        __syncthreads();
        if (t < 64)
            l_s[t] = l_s[t] * al_s[t] + rsum[t] + rsum[64 + t] + rsum[128 + t] + rsum[192 + t];
        {
            float a0 = al_s[r0], a1 = al_s[r1];
#pragma unroll
            for (int nf = 0; nf < 4; nf++) {
                oacc[nf][0] *= a0; oacc[nf][1] *= a0;
                oacc[nf][2] *= a1; oacc[nf][3] *= a1;
            }
        }
        // ---- O += P V  (warp: rows wq*16, d-cols wk*32) ----
        const uint32_t vhb = VHOF + (uint32_t)s * 34816;
#pragma unroll
        for (int ks = 0; ks < 4; ks++) {
            uint32_t pa = smb + PHOF + (uint32_t)((wq * 16 + (g & 1) * 8 + r8) * 72
                                                  + ks * 16 + (g >> 1) * 8) * 2;
            uint32_t ph4[4], pl4[4];
            ldsm4(ph4, pa);
            ldsm4(pl4, pa + (PLOF - PHOF));
#pragma unroll
            for (int nt = 0; nt < 2; nt++) {
                uint32_t vb = smb + vhb + (uint32_t)((ks * 16 + (L & 15)) * 136
                                                     + wk * 32 + nt * 16 + (L >> 4) * 8) * 2;
                uint32_t vh4[4], vl4[4];
                ldsm4t(vh4, vb);
                ldsm4t(vl4, vb + 17408);
                mma16816(oacc[nt * 2], ph4, vh4);
                mma16816(oacc[nt * 2], ph4, vl4);
                mma16816(oacc[nt * 2], pl4, vh4);
                mma16816(oacc[nt * 2 + 1], ph4, vh4 + 2);
                mma16816(oacc[nt * 2 + 1], ph4, vl4 + 2);
                mma16816(oacc[nt * 2 + 1], pl4, vh4 + 2);
            }
        }
        // ---- build next tile's K/V while tensor pipe drains ----
        CPW1();
        __syncthreads();
        if (tile + 1 < NTILE)
            rope_split(tile + 1, (tile & 1) ? RAW0 : RAW1, (tile + 1) & 1);
        __syncthreads();
    }

    // ---- epilogue ----
    {
        float inv0 = 1.0f / l_s[r0], inv1 = 1.0f / l_s[r1];
#pragma unroll
        for (int nf = 0; nf < 4; nf++) {
            int d = wk * 32 + nf * 8 + (L & 3) * 2;
            size_t o0 = ((size_t)b * QL + r0) * HID + h * HD + d;
            size_t o1 = ((size_t)b * QL + r1) * HID + h * HD + d;
            *(float2*)&out[o0] = make_float2(oacc[nf][0] * inv0, oacc[nf][1] * inv0);
            *(float2*)&out[o1] = make_float2(oacc[nf][2] * inv1, oacc[nf][3] * inv1);
        }
    }
}

// ---------------------------------------------------------------------------
extern "C" void kernel_launch(void* const* d_in, const int* in_sizes, int n_in,
                              void* d_out, int out_size)
{
    const float* hidden = (const float*)d_in[0];
    const float* target = (const float*)d_in[1];
    const float* cosp   = (const float*)d_in[2];
    const float* sinp   = (const float*)d_in[3];
    const float* Wqkv   = (const float*)d_in[4];
    const float* Wo     = (const float*)d_in[5];
    const float* qnw    = (const float*)d_in[6];
    float* out = (float*)d_out;

    float *qproj, *qrope, *attn;
    cudaGetSymbolAddress((void**)&qproj, g_qproj);
    cudaGetSymbolAddress((void**)&qrope, g_q);
    cudaGetSymbolAddress((void**)&attn,  g_attn);

    cudaFuncSetAttribute(gemm_bf16s, cudaFuncAttributeMaxDynamicSharedMemorySize, GSMEM);
    cudaFuncSetAttribute(attn_kernel, cudaFuncAttributeMaxDynamicSharedMemorySize, ATT_SMEM);

    dim3 gg(HID / 64, (BB * QL) / 128);  // (64, 2)
    gemm_bf16s<<<gg, 256, GSMEM>>>(hidden, Wqkv, qproj, HID, HID, 3 * HID);

    qnorm_rope_kernel<<<BB * QL * NH, 128>>>(qproj, qnw, cosp, sinp, qrope);

    dim3 ga(NH, BB);
    attn_kernel<<<ga, 512, ATT_SMEM>>>(qrope, target, hidden, cosp, sinp, attn);

    gemm_bf16s<<<gg, 256, GSMEM>>>(attn, Wo, out, HID, HID, HID);
}

// round 6
// speedup vs baseline: 3.3994x; 1.1433x over previous
#include <cuda_runtime.h>
#include <cstdint>
#include <math.h>

#define NH   32
#define HD   128
#define BB   4
#define QL   64
#define CTX  4096
#define HID  4096
#define TOTAL_KV (CTX + QL)
#define NTILE (TOTAL_KV / 64)    // 65

__device__ float g_qproj[BB * QL * HID];
__device__ float g_q[BB * NH * QL * HD];
__device__ float g_attn[BB * QL * HID];

__device__ __forceinline__ uint32_t smem_u32(const void* p) {
    uint32_t a;
    asm("{ .reg .u64 t; cvta.to.shared.u64 t, %1; cvt.u32.u64 %0, t; }" : "=r"(a) : "l"(p));
    return a;
}
__device__ __forceinline__ void ldsm4(uint32_t* r, uint32_t a) {
    asm volatile("ldmatrix.sync.aligned.m8n8.x4.shared.b16 {%0,%1,%2,%3}, [%4];"
        : "=r"(r[0]), "=r"(r[1]), "=r"(r[2]), "=r"(r[3]) : "r"(a));
}
__device__ __forceinline__ void ldsm4t(uint32_t* r, uint32_t a) {
    asm volatile("ldmatrix.sync.aligned.m8n8.x4.trans.shared.b16 {%0,%1,%2,%3}, [%4];"
        : "=r"(r[0]), "=r"(r[1]), "=r"(r[2]), "=r"(r[3]) : "r"(a));
}
__device__ __forceinline__ void mma16816(float* c, const uint32_t* a, const uint32_t* b) {
    asm volatile(
        "mma.sync.aligned.m16n8k16.row.col.f32.bf16.bf16.f32 "
        "{%0,%1,%2,%3}, {%4,%5,%6,%7}, {%8,%9}, {%0,%1,%2,%3};"
        : "+f"(c[0]), "+f"(c[1]), "+f"(c[2]), "+f"(c[3])
        : "r"(a[0]), "r"(a[1]), "r"(a[2]), "r"(a[3]), "r"(b[0]), "r"(b[1]));
}
__device__ __forceinline__ void split_pack(float e0, float e1, uint32_t& hi, uint32_t& lo) {
    uint32_t h;
    asm("cvt.rn.bf16x2.f32 %0, %1, %2;" : "=r"(h) : "f"(e1), "f"(e0));
    float f0 = __uint_as_float(h << 16);
    float f1 = __uint_as_float(h & 0xffff0000u);
    uint32_t l;
    asm("cvt.rn.bf16x2.f32 %0, %1, %2;" : "=r"(l) : "f"(e1 - f1), "f"(e0 - f0));
    hi = h; lo = l;
}
#define CPA16(d, s) asm volatile("cp.async.cg.shared.global [%0], [%1], 16;" :: "r"(d), "l"(s))
#define CPC()  asm volatile("cp.async.commit_group;" ::: "memory")
#define CPW1() asm volatile("cp.async.wait_group 1;" ::: "memory")

// ===========================================================================
// bf16-split GEMM (unchanged, validated): C[256,N] = A[256,K] @ W[K,N]
// ===========================================================================
#define AST 40
#define WST 72
#define ABYTES (128 * AST * 2)
#define WBYTES (32 * WST * 2)
#define STAGE  (2 * ABYTES + 2 * WBYTES)
#define GSMEM  (2 * STAGE)

#define GEMM_LDG(c) do { \
  _Pragma("unroll") for (int q = 0; q < 4; q++) { int i = t + q * 256; \
    ra[q] = *(const float4*)(A + (size_t)(m0 + (i >> 3)) * K + (c) * 32 + (i & 7) * 4); } \
  _Pragma("unroll") for (int q = 0; q < 2; q++) { int i = t + q * 256; \
    rw[q] = *(const float4*)(W + (size_t)((c) * 32 + (i >> 4)) * ldb + n0 + (i & 15) * 4); } \
} while (0)

#define GEMM_STS(bufp) do { \
  _Pragma("unroll") for (int q = 0; q < 4; q++) { int i = t + q * 256; \
    int row = i >> 3, kc = (i & 7) * 4; uint32_t h0, l0, h1, l1; \
    split_pack(ra[q].x, ra[q].y, h0, l0); split_pack(ra[q].z, ra[q].w, h1, l1); \
    uint32_t off = (uint32_t)(row * AST + kc) * 2; \
    *(uint2*)((bufp) + off) = make_uint2(h0, h1); \
    *(uint2*)((bufp) + ABYTES + off) = make_uint2(l0, l1); } \
  _Pragma("unroll") for (int q = 0; q < 2; q++) { int i = t + q * 256; \
    int kr = i >> 4, nc = (i & 15) * 4; uint32_t h0, l0, h1, l1; \
    split_pack(rw[q].x, rw[q].y, h0, l0); split_pack(rw[q].z, rw[q].w, h1, l1); \
    uint32_t off = (uint32_t)(kr * WST + nc) * 2; \
    *(uint2*)((bufp) + 2 * ABYTES + off) = make_uint2(h0, h1); \
    *(uint2*)((bufp) + 2 * ABYTES + WBYTES + off) = make_uint2(l0, l1); } \
} while (0)

__global__ __launch_bounds__(256) void gemm_bf16s(
    const float* __restrict__ A, const float* __restrict__ W,
    float* __restrict__ C, int K, int N, int ldb)
{
    extern __shared__ __align__(16) char smc[];
    const uint32_t smb = smem_u32(smc);
    const int t = threadIdx.x, w = t >> 5, L = t & 31, g = L >> 3, r8 = L & 7;
    const int wm = w >> 1, wn = w & 1;
    const int m0 = blockIdx.y * 128, n0 = blockIdx.x * 64;
    const int NCH = K / 32;

    float4 ra[4]; float4 rw[2];
    float acc[2][4][4] = {};

    GEMM_LDG(0);
    GEMM_STS(smc);
    __syncthreads();
    if (NCH > 1) GEMM_LDG(1);

    for (int c = 0; c < NCH; c++) {
        const uint32_t sb = smb + (uint32_t)(c & 1) * STAGE;
#pragma unroll
        for (int ks = 0; ks < 2; ks++) {
            uint32_t ah[2][4], al[2][4], bh[4][2], bl[4][2];
#pragma unroll
            for (int mf = 0; mf < 2; mf++) {
                uint32_t ad = sb + (uint32_t)((wm * 32 + mf * 16 + (g & 1) * 8 + r8) * AST
                                              + ks * 16 + (g >> 1) * 8) * 2;
                ldsm4(ah[mf], ad);
                ldsm4(al[mf], ad + ABYTES);
            }
#pragma unroll
            for (int nt = 0; nt < 2; nt++) {
                int kk = ks * 16 + (L & 15);
                int nn = wn * 32 + nt * 16 + ((L >> 4) << 3);
                uint32_t bd = sb + 2 * ABYTES + (uint32_t)(kk * WST + nn) * 2;
                uint32_t r4[4];
                ldsm4t(r4, bd);
                bh[nt * 2][0] = r4[0]; bh[nt * 2][1] = r4[1];
                bh[nt * 2 + 1][0] = r4[2]; bh[nt * 2 + 1][1] = r4[3];
                ldsm4t(r4, bd + WBYTES);
                bl[nt * 2][0] = r4[0]; bl[nt * 2][1] = r4[1];
                bl[nt * 2 + 1][0] = r4[2]; bl[nt * 2 + 1][1] = r4[3];
            }
#pragma unroll
            for (int mf = 0; mf < 2; mf++)
#pragma unroll
                for (int nf = 0; nf < 4; nf++) {
                    mma16816(acc[mf][nf], ah[mf], bh[nf]);
                    mma16816(acc[mf][nf], ah[mf], bl[nf]);
                    mma16816(acc[mf][nf], al[mf], bh[nf]);
                }
        }
        if (c + 1 < NCH) {
            GEMM_STS(smc + ((c + 1) & 1) * STAGE);
            if (c + 2 < NCH) GEMM_LDG(c + 2);
        }
        __syncthreads();
    }

#pragma unroll
    for (int mf = 0; mf < 2; mf++)
#pragma unroll
        for (int nf = 0; nf < 4; nf++) {
            int col = n0 + wn * 32 + nf * 8 + (L & 3) * 2;
            int r0 = m0 + wm * 32 + mf * 16 + (L >> 2);
            *(float2*)&C[(size_t)r0 * N + col] = make_float2(acc[mf][nf][0], acc[mf][nf][1]);
            *(float2*)&C[(size_t)(r0 + 8) * N + col] = make_float2(acc[mf][nf][2], acc[mf][nf][3]);
        }
}

// ---------------------------------------------------------------------------
// Fused double-RMSNorm + RoPE on Q (unchanged).
// ---------------------------------------------------------------------------
__global__ __launch_bounds__(128) void qnorm_rope_kernel(
    const float* __restrict__ qproj, const float* __restrict__ w,
    const float* __restrict__ cosp, const float* __restrict__ sinp,
    float* __restrict__ qout)
{
    const int blk = blockIdx.x;
    const int h = blk & 31;
    const int m = blk >> 5;
    const int b = m >> 6, q = m & 63;
    const int d = threadIdx.x;

    __shared__ float red[4];
    __shared__ float zbuf[128];

    float x = qproj[(size_t)m * HID + h * HD + d];
    float v = x * x;
#pragma unroll
    for (int o = 16; o > 0; o >>= 1) v += __shfl_down_sync(0xffffffffu, v, o);
    if ((d & 31) == 0) red[d >> 5] = v;
    __syncthreads();
    float mean1 = (red[0] + red[1] + red[2] + red[3]) * (1.0f / 128.0f);
    float y = x * rsqrtf(mean1 + 1e-6f) * w[d];
    __syncthreads();
    v = y * y;
#pragma unroll
    for (int o = 16; o > 0; o >>= 1) v += __shfl_down_sync(0xffffffffu, v, o);
    if ((d & 31) == 0) red[d >> 5] = v;
    __syncthreads();
    float mean2 = (red[0] + red[1] + red[2] + red[3]) * (1.0f / 128.0f);
    float z = y * rsqrtf(mean2 + 1e-6f) * w[d];
    zbuf[d] = z;
    __syncthreads();
    const int pos = CTX + q;
    float rot = (d < 64) ? -zbuf[d + 64] : zbuf[d - 64];
    qout[(((size_t)(b * NH + h) * QL) + q) * HD + d] =
        z * cosp[(size_t)pos * HD + d] + rot * sinp[(size_t)pos * HD + d];
}

// ===========================================================================
// Flash attention v3: K stored [pos][d] (non-trans ldsm B), register m/l,
// 3 barriers/tile, merged rope+split, cp.async double-buffered.
// ===========================================================================
#define RAW0 0
#define RAW1 32768
#define KHO  65536          // KH(s) = KHO + s*34816, KL = KH + 17408
#define VHO  135168         // VH(s) = VHO + s*34816, VL = VH + 17408
#define PHO  204800         // [64][72] bf16 hi
#define PLO  214016         // lo
#define WMX  223232         // float [4][64]
#define WSM  224256         // float [4][64]
#define ATT_SMEM 225280

__global__ __launch_bounds__(512, 1) void attn_kernel(
    const float* __restrict__ qin, const float* __restrict__ target,
    const float* __restrict__ hidden, const float* __restrict__ cosp,
    const float* __restrict__ sinp, float* __restrict__ out)
{
    extern __shared__ __align__(16) char smc[];
    const uint32_t smb = smem_u32(smc);
    float* wmx = (float*)(smc + WMX);
    float* wsm = (float*)(smc + WSM);

    const int h = blockIdx.x, b = blockIdx.y;
    const int t = threadIdx.x, w = t >> 5, L = t & 31, g = L >> 3, r8 = L & 7;
    const int wq = w >> 2, wk = w & 3;
    const float scale = 0.08838834764831845f;

    // ---- stage Q (hi/lo) in RAW area, hoist fragments, then release ----
    const float* qb = qin + ((size_t)(b * NH + h) * QL) * HD;
#pragma unroll
    for (int i = 0; i < 8; i++) {
        int idx = t + i * 512, row = idx >> 6, d0 = (idx & 63) * 2;
        float e0 = qb[row * HD + d0] * scale, e1 = qb[row * HD + d0 + 1] * scale;
        uint32_t hw, lw; split_pack(e0, e1, hw, lw);
        *(uint32_t*)(smc + (uint32_t)(row * 136 + d0) * 2) = hw;
        *(uint32_t*)(smc + 17408 + (uint32_t)(row * 136 + d0) * 2) = lw;
    }
    __syncthreads();
    uint32_t qhf[8][4], qlf[8][4];
#pragma unroll
    for (int ds = 0; ds < 8; ds++) {
        uint32_t ad = smb + (uint32_t)((wq * 16 + (g & 1) * 8 + r8) * 136
                                       + ds * 16 + (g >> 1) * 8) * 2;
        ldsm4(qhf[ds], ad);
        ldsm4(qlf[ds], ad + 17408);
    }
    __syncthreads();

    auto cp_tile = [&](int tn, uint32_t dstoff) {
        const int p0 = tn * 64;
#pragma unroll
        for (int q = 0; q < 4; q++) {
            int idx = t + q * 512, row = idx >> 5, c16 = idx & 31;
            int p = p0 + row;
            const float* src = (p < CTX)
                ? (target + ((size_t)b * CTX + p) * HID + h * HD + c16 * 4)
                : (hidden + ((size_t)b * QL + (p - CTX)) * HID + h * HD + c16 * 4);
            CPA16(smb + dstoff + (uint32_t)(row * 512 + c16 * 16), src);
        }
    };
    // merged V-split + K-rope-split; K and V both [pos][d], 32-bit stores
    auto rope_split = [&](int tn, uint32_t rawoff, int s) {
        const float* rawf = (const float*)(smc + rawoff);
        const int p0 = tn * 64;
        char* kh = smc + KHO + (uint32_t)s * 34816;
        char* vh = smc + VHO + (uint32_t)s * 34816;
#pragma unroll
        for (int i = 0; i < 8; i++) {
            int idx = t + i * 512, pos = idx >> 6, d0 = (idx & 63) * 2;
            float2 xv = *(const float2*)(rawf + pos * 128 + d0);
            uint32_t hw, lw; split_pack(xv.x, xv.y, hw, lw);
            uint32_t off = (uint32_t)(pos * 136 + d0) * 2;
            *(uint32_t*)(vh + off) = hw;
            *(uint32_t*)(vh + 17408 + off) = lw;
            float2 xr = (d0 < 64) ? *(const float2*)(rawf + pos * 128 + d0 + 64)
                                  : *(const float2*)(rawf + pos * 128 + d0 - 64);
            float rr0 = (d0 < 64) ? -xr.x : xr.x;
            float rr1 = (d0 < 64) ? -xr.y : xr.y;
            int p = p0 + pos;
            float2 cv = *(const float2*)(cosp + (size_t)p * HD + d0);
            float2 sv = *(const float2*)(sinp + (size_t)p * HD + d0);
            float e0 = xv.x * cv.x + rr0 * sv.x;
            float e1 = xv.y * cv.y + rr1 * sv.y;
            split_pack(e0, e1, hw, lw);
            *(uint32_t*)(kh + off) = hw;
            *(uint32_t*)(kh + 17408 + off) = lw;
        }
    };

    // prologue
    cp_tile(0, RAW0); CPC();
    cp_tile(1, RAW1); CPC();
    CPW1();
    __syncthreads();
    rope_split(0, RAW0, 0);
    __syncthreads();

    float oacc[4][4] = {};
    const int r0 = wq * 16 + (L >> 2), r1 = r0 + 8;
    float m0r = -1e30f, m1r = -1e30f, l0r = 0.0f, l1r = 0.0f;

    for (int tile = 0; tile < NTILE; tile++) {
        const int s = tile & 1;
        if (tile + 2 < NTILE) cp_tile(tile + 2, s ? RAW1 : RAW0);
        CPC();

        // ---- S = Q K^T (B-operand: non-trans ldsm on K[pos][d]) ----
        const uint32_t khb = smb + KHO + (uint32_t)s * 34816;
        float sacc[2][4] = {};
#pragma unroll
        for (int ds = 0; ds < 8; ds++) {
            uint32_t bd = khb + (uint32_t)((wk * 16 + (g >> 1) * 8 + r8) * 136
                                           + ds * 16 + (g & 1) * 8) * 2;
            uint32_t bh4[4], bl4[4];
            ldsm4(bh4, bd);
            ldsm4(bl4, bd + 17408);
            mma16816(sacc[0], qhf[ds], bh4);
            mma16816(sacc[0], qhf[ds], bl4);
            mma16816(sacc[0], qlf[ds], bh4);
            mma16816(sacc[1], qhf[ds], bh4 + 2);
            mma16816(sacc[1], qhf[ds], bl4 + 2);
            mma16816(sacc[1], qlf[ds], bh4 + 2);
        }
        // warp-local row max over this warp's 16 keys
        float mx0 = fmaxf(fmaxf(sacc[0][0], sacc[0][1]), fmaxf(sacc[1][0], sacc[1][1]));
        float mx1 = fmaxf(fmaxf(sacc[0][2], sacc[0][3]), fmaxf(sacc[1][2], sacc[1][3]));
        mx0 = fmaxf(mx0, __shfl_xor_sync(0xffffffffu, mx0, 1));
        mx0 = fmaxf(mx0, __shfl_xor_sync(0xffffffffu, mx0, 2));
        mx1 = fmaxf(mx1, __shfl_xor_sync(0xffffffffu, mx1, 1));
        mx1 = fmaxf(mx1, __shfl_xor_sync(0xffffffffu, mx1, 2));
        if ((L & 3) == 0) { wmx[wk * 64 + r0] = mx0; wmx[wk * 64 + r1] = mx1; }
        __syncthreads();                                       // bar1

        // global max + alpha (redundant per warp, register-resident)
        float gm0 = fmaxf(fmaxf(wmx[r0], wmx[64 + r0]), fmaxf(wmx[128 + r0], wmx[192 + r0]));
        float gm1 = fmaxf(fmaxf(wmx[r1], wmx[64 + r1]), fmaxf(wmx[128 + r1], wmx[192 + r1]));
        float mn0 = fmaxf(m0r, gm0), mn1 = fmaxf(m1r, gm1);
        float al0 = __expf(m0r - mn0), al1 = __expf(m1r - mn1);
        m0r = mn0; m1r = mn1;

        // exp, split-store P, partial row sums
        float s0 = 0.f, s1 = 0.f;
#pragma unroll
        for (int nf = 0; nf < 2; nf++) {
            float e0 = __expf(sacc[nf][0] - mn0), e1 = __expf(sacc[nf][1] - mn0);
            float e2 = __expf(sacc[nf][2] - mn1), e3 = __expf(sacc[nf][3] - mn1);
            s0 += e0 + e1; s1 += e2 + e3;
            int col = wk * 16 + nf * 8 + (L & 3) * 2;
            uint32_t hw, lw;
            split_pack(e0, e1, hw, lw);
            *(uint32_t*)(smc + PHO + (uint32_t)(r0 * 72 + col) * 2) = hw;
            *(uint32_t*)(smc + PLO + (uint32_t)(r0 * 72 + col) * 2) = lw;
            split_pack(e2, e3, hw, lw);
            *(uint32_t*)(smc + PHO + (uint32_t)(r1 * 72 + col) * 2) = hw;
            *(uint32_t*)(smc + PLO + (uint32_t)(r1 * 72 + col) * 2) = lw;
        }
        s0 += __shfl_xor_sync(0xffffffffu, s0, 1);
        s0 += __shfl_xor_sync(0xffffffffu, s0, 2);
        s1 += __shfl_xor_sync(0xffffffffu, s1, 1);
        s1 += __shfl_xor_sync(0xffffffffu, s1, 2);
        if ((L & 3) == 0) { wsm[wk * 64 + r0] = s0; wsm[wk * 64 + r1] = s1; }
        CPW1();                                                 // own cp(i+1) done
        __syncthreads();                                        // bar2 (P+sums+cp visible)

        l0r = l0r * al0 + wsm[r0] + wsm[64 + r0] + wsm[128 + r0] + wsm[192 + r0];
        l1r = l1r * al1 + wsm[r1] + wsm[64 + r1] + wsm[128 + r1] + wsm[192 + r1];
#pragma unroll
        for (int nf = 0; nf < 4; nf++) {
            oacc[nf][0] *= al0; oacc[nf][1] *= al0;
            oacc[nf][2] *= al1; oacc[nf][3] *= al1;
        }

        // ---- O += P V ----
        const uint32_t vhb = smb + VHO + (uint32_t)s * 34816;
#pragma unroll
        for (int ks = 0; ks < 4; ks++) {
            uint32_t pa = smb + PHO + (uint32_t)((wq * 16 + (g & 1) * 8 + r8) * 72
                                                 + ks * 16 + (g >> 1) * 8) * 2;
            uint32_t ph4[4], pl4[4];
            ldsm4(ph4, pa);
            ldsm4(pl4, pa + (PLO - PHO));
#pragma unroll
            for (int nt = 0; nt < 2; nt++) {
                uint32_t vb = vhb + (uint32_t)((ks * 16 + (L & 15)) * 136
                                               + wk * 32 + nt * 16 + (L >> 4) * 8) * 2;
                uint32_t vh4[4], vl4[4];
                ldsm4t(vh4, vb);
                ldsm4t(vl4, vb + 17408);
                mma16816(oacc[nt * 2], ph4, vh4);
                mma16816(oacc[nt * 2], ph4, vl4);
                mma16816(oacc[nt * 2], pl4, vh4);
                mma16816(oacc[nt * 2 + 1], ph4, vh4 + 2);
                mma16816(oacc[nt * 2 + 1], ph4, vl4 + 2);
                mma16816(oacc[nt * 2 + 1], pl4, vh4 + 2);
            }
        }

        // ---- next tile K/V build (overlaps PV drain across warps) ----
        if (tile + 1 < NTILE) {
            rope_split(tile + 1, s ? RAW0 : RAW1, (tile + 1) & 1);
            __syncthreads();                                    // bar3
        }
    }

    // ---- epilogue ----
    {
        float inv0 = 1.0f / l0r, inv1 = 1.0f / l1r;
#pragma unroll
        for (int nf = 0; nf < 4; nf++) {
            int d = wk * 32 + nf * 8 + (L & 3) * 2;
            size_t o0 = ((size_t)b * QL + r0) * HID + h * HD + d;
            size_t o1 = ((size_t)b * QL + r1) * HID + h * HD + d;
            *(float2*)&out[o0] = make_float2(oacc[nf][0] * inv0, oacc[nf][1] * inv0);
            *(float2*)&out[o1] = make_float2(oacc[nf][2] * inv1, oacc[nf][3] * inv1);
        }
    }
}

// ---------------------------------------------------------------------------
extern "C" void kernel_launch(void* const* d_in, const int* in_sizes, int n_in,
                              void* d_out, int out_size)
{
    const float* hidden = (const float*)d_in[0];
    const float* target = (const float*)d_in[1];
    const float* cosp   = (const float*)d_in[2];
    const float* sinp   = (const float*)d_in[3];
    const float* Wqkv   = (const float*)d_in[4];
    const float* Wo     = (const float*)d_in[5];
    const float* qnw    = (const float*)d_in[6];
    float* out = (float*)d_out;

    float *qproj, *qrope, *attn;
    cudaGetSymbolAddress((void**)&qproj, g_qproj);
    cudaGetSymbolAddress((void**)&qrope, g_q);
    cudaGetSymbolAddress((void**)&attn,  g_attn);

    cudaFuncSetAttribute(gemm_bf16s, cudaFuncAttributeMaxDynamicSharedMemorySize, GSMEM);
    cudaFuncSetAttribute(attn_kernel, cudaFuncAttributeMaxDynamicSharedMemorySize, ATT_SMEM);

    dim3 gg(HID / 64, (BB * QL) / 128);  // (64, 2)
    gemm_bf16s<<<gg, 256, GSMEM>>>(hidden, Wqkv, qproj, HID, HID, 3 * HID);

    qnorm_rope_kernel<<<BB * QL * NH, 128>>>(qproj, qnw, cosp, sinp, qrope);

    dim3 ga(NH, BB);
    attn_kernel<<<ga, 512, ATT_SMEM>>>(qrope, target, hidden, cosp, sinp, attn);

    gemm_bf16s<<<gg, 256, GSMEM>>>(attn, Wo, out, HID, HID, HID);
}